// round 2
// baseline (speedup 1.0000x reference)
#include <cuda_runtime.h>
#include <math.h>

// Fixed problem shape (from reference): N=100000, E=1600000, IN_F=128, H=4, C=32.
#define MAXN 100000
#define MAXE 1600000
#define F 128      // IN_F == H*C == 128
#define HEADS 4
#define NEG_SLOPE 0.2f

// Scratch (allocation-free rule: __device__ globals)
__device__ __align__(16) float g_h[MAXN * F];                  // 51.2 MB projected features
__device__ __align__(16) float g_asrc[MAXN * HEADS];           // per-node src attention half
__device__ __align__(16) float g_adst[MAXN * HEADS];           // per-node dst attention half
__device__ __align__(16) float g_den[MAXN * HEADS];            // softmax denominators
__device__ __align__(16) float g_p[(MAXE + MAXN) * HEADS];     // per-edge unnormalized exp

// ---------------------------------------------------------------------------
// Kernel 1: init output with bias, zero denominators
// ---------------------------------------------------------------------------
__global__ void init_kernel(float* __restrict__ out, const float* __restrict__ bias, int N) {
    int tid = blockIdx.x * blockDim.x + threadIdx.x;
    int total = N * F;
    if (tid < total) {
        out[tid] = bias[tid & (F - 1)];
    }
    if (tid < N * HEADS) {
        g_den[tid] = 0.0f;
    }
}

// ---------------------------------------------------------------------------
// Kernel 2: h = x @ W  (N x 128 @ 128 x 128), fused a_src/a_dst epilogue.
// Block = 128 threads (one per output column), TM=16 rows per block.
// Warp w owns columns [32w,32w+32) == head w, so the attention-half dot is a
// pure warp shuffle reduction.
// ---------------------------------------------------------------------------
__global__ void proj_kernel(const float* __restrict__ x,
                            const float* __restrict__ W,
                            const float* __restrict__ att_src,
                            const float* __restrict__ att_dst,
                            int N) {
    const int TM = 16;
    __shared__ float xs[TM][F];

    int row0 = blockIdx.x * TM;
    int col  = threadIdx.x;            // 0..127

    // Load x tile [TM x 128] (coalesced along k)
    #pragma unroll
    for (int i = 0; i < TM; i++) {
        int r = row0 + i;
        xs[i][col] = (r < N) ? x[r * F + col] : 0.0f;
    }
    __syncthreads();

    float acc[TM];
    #pragma unroll
    for (int m = 0; m < TM; m++) acc[m] = 0.0f;

    #pragma unroll 8
    for (int k = 0; k < F; k += 4) {
        float w0 = W[(k + 0) * F + col];
        float w1 = W[(k + 1) * F + col];
        float w2 = W[(k + 2) * F + col];
        float w3 = W[(k + 3) * F + col];
        #pragma unroll
        for (int m = 0; m < TM; m++) {
            float4 xv = *reinterpret_cast<const float4*>(&xs[m][k]);
            acc[m] = fmaf(xv.x, w0, acc[m]);
            acc[m] = fmaf(xv.y, w1, acc[m]);
            acc[m] = fmaf(xv.z, w2, acc[m]);
            acc[m] = fmaf(xv.w, w3, acc[m]);
        }
    }

    int head = col >> 5;        // warp id == head id
    int lane = col & 31;
    float as = att_src[head * 32 + lane];
    float ad = att_dst[head * 32 + lane];

    #pragma unroll
    for (int m = 0; m < TM; m++) {
        int r = row0 + m;
        if (r < N) {
            g_h[r * F + col] = acc[m];
            float s = acc[m] * as;
            float d = acc[m] * ad;
            #pragma unroll
            for (int o = 16; o > 0; o >>= 1) {
                s += __shfl_xor_sync(0xFFFFFFFFu, s, o);
                d += __shfl_xor_sync(0xFFFFFFFFu, d, o);
            }
            if (lane == 0) {
                g_asrc[r * HEADS + head] = s;
                g_adst[r * HEADS + head] = d;
            }
        }
    }
}

// ---------------------------------------------------------------------------
// Kernel 3: per-edge p = exp(leaky_relu(a_src[s] + a_dst[d])), accumulate denom.
// Softmax is shift-invariant, so the segment_max pass is skipped (logits are
// O(+-10); fp32 exp is safe and alpha = p / sum(p) is identical).
// Edges E..E+N-1 are the implicit self-loops.
// ---------------------------------------------------------------------------
__device__ __forceinline__ float lrelu(float v) {
    return v > 0.0f ? v : NEG_SLOPE * v;
}

__global__ void edge_sum_kernel(const int* __restrict__ ei, int E, int N) {
    int e = blockIdx.x * blockDim.x + threadIdx.x;
    int total = E + N;
    if (e >= total) return;
    int s, d;
    if (e < E) {
        s = ei[e];
        d = ei[E + e];
    } else {
        s = d = e - E;
    }
    float4 as = *reinterpret_cast<const float4*>(&g_asrc[s * HEADS]);
    float4 ad = *reinterpret_cast<const float4*>(&g_adst[d * HEADS]);
    float4 p;
    p.x = __expf(lrelu(as.x + ad.x));
    p.y = __expf(lrelu(as.y + ad.y));
    p.z = __expf(lrelu(as.z + ad.z));
    p.w = __expf(lrelu(as.w + ad.w));
    // __expf max rel err ~2^-22 on this range; well within 1e-3 tolerance.
    *reinterpret_cast<float4*>(&g_p[(size_t)e * HEADS]) = p;
    float* dst = &g_den[d * HEADS];
    asm volatile("red.global.add.v4.f32 [%0], {%1,%2,%3,%4};"
                 :: "l"(dst), "f"(p.x), "f"(p.y), "f"(p.z), "f"(p.w)
                 : "memory");
}

// ---------------------------------------------------------------------------
// Kernel 4: scatter. One warp per edge; lane l handles float4 at offset 4l
// (head = l/8). out[dst] += h[src] * alpha via vector global reductions.
// ---------------------------------------------------------------------------
__global__ void scatter_kernel(const int* __restrict__ ei,
                               float* __restrict__ out, int E, int N) {
    int gid  = blockIdx.x * blockDim.x + threadIdx.x;
    int eidx = gid >> 5;
    int lane = threadIdx.x & 31;
    int total = E + N;
    if (eidx >= total) return;

    int s, d;
    if (eidx < E) {
        s = ei[eidx];
        d = ei[E + eidx];
    } else {
        s = d = eidx - E;
    }

    int head = lane >> 3;
    float p     = g_p[(size_t)eidx * HEADS + head];
    float denom = g_den[d * HEADS + head];
    float alpha = p / (denom + 1e-16f);

    float4 hv = *reinterpret_cast<const float4*>(&g_h[s * F + lane * 4]);
    float4 r;
    r.x = hv.x * alpha;
    r.y = hv.y * alpha;
    r.z = hv.z * alpha;
    r.w = hv.w * alpha;

    float* dst = &out[d * F + lane * 4];
    asm volatile("red.global.add.v4.f32 [%0], {%1,%2,%3,%4};"
                 :: "l"(dst), "f"(r.x), "f"(r.y), "f"(r.z), "f"(r.w)
                 : "memory");
}

// ---------------------------------------------------------------------------
// Launch
// ---------------------------------------------------------------------------
extern "C" void kernel_launch(void* const* d_in, const int* in_sizes, int n_in,
                              void* d_out, int out_size) {
    const float* x       = (const float*)d_in[0];
    const int*   ei      = (const int*)d_in[1];
    const float* W       = (const float*)d_in[2];
    const float* att_src = (const float*)d_in[3];
    const float* att_dst = (const float*)d_in[4];
    const float* bias    = (const float*)d_in[5];
    float*       out     = (float*)d_out;

    int N = in_sizes[0] / F;     // 100000
    int E = in_sizes[1] / 2;     // 1600000
    int total = E + N;           // edges incl. self-loops

    init_kernel<<<(N * F + 255) / 256, 256>>>(out, bias, N);
    proj_kernel<<<(N + 15) / 16, 128>>>(x, W, att_src, att_dst, N);
    edge_sum_kernel<<<(total + 255) / 256, 256>>>(ei, E, N);
    long long sthreads = (long long)total * 32;
    int sblocks = (int)((sthreads + 255) / 256);
    scatter_kernel<<<sblocks, 256>>>(ei, out, E, N);
}

// round 3
// speedup vs baseline: 1.4116x; 1.4116x over previous
#include <cuda_runtime.h>
#include <math.h>

// Fixed problem shape: N=100000, E=1600000, IN_F=128, H=4, C=32.
#define MAXN 100000
#define MAXE 1600000
#define F 128
#define HEADS 4
#define NEG_SLOPE 0.2f

__device__ __align__(16) float g_h[MAXN * F];
__device__ __align__(16) float g_asrc[MAXN * HEADS];
__device__ __align__(16) float g_adst[MAXN * HEADS];
__device__ __align__(16) float g_den[MAXN * HEADS];
__device__ __align__(16) float g_p[(MAXE + MAXN) * HEADS];

// ---------------------------------------------------------------------------
// Kernel 1: init output with bias (vectorized), zero denominators
// ---------------------------------------------------------------------------
__global__ void init_kernel(float4* __restrict__ out, const float4* __restrict__ bias, int N) {
    int tid = blockIdx.x * blockDim.x + threadIdx.x;
    int total4 = N * (F / 4);
    if (tid < total4) {
        out[tid] = bias[tid & (F / 4 - 1)];
    }
    if (tid < N) {
        *reinterpret_cast<float4*>(&g_den[tid * HEADS]) = make_float4(0.f, 0.f, 0.f, 0.f);
    }
}

// ---------------------------------------------------------------------------
// Kernel 2: h = x @ W with fused a_src/a_dst epilogue (unchanged from R2).
// ---------------------------------------------------------------------------
__global__ void proj_kernel(const float* __restrict__ x,
                            const float* __restrict__ W,
                            const float* __restrict__ att_src,
                            const float* __restrict__ att_dst,
                            int N) {
    const int TM = 16;
    __shared__ float xs[TM][F];

    int row0 = blockIdx.x * TM;
    int col  = threadIdx.x;

    #pragma unroll
    for (int i = 0; i < TM; i++) {
        int r = row0 + i;
        xs[i][col] = (r < N) ? x[r * F + col] : 0.0f;
    }
    __syncthreads();

    float acc[TM];
    #pragma unroll
    for (int m = 0; m < TM; m++) acc[m] = 0.0f;

    #pragma unroll 8
    for (int k = 0; k < F; k += 4) {
        float w0 = W[(k + 0) * F + col];
        float w1 = W[(k + 1) * F + col];
        float w2 = W[(k + 2) * F + col];
        float w3 = W[(k + 3) * F + col];
        #pragma unroll
        for (int m = 0; m < TM; m++) {
            float4 xv = *reinterpret_cast<const float4*>(&xs[m][k]);
            acc[m] = fmaf(xv.x, w0, acc[m]);
            acc[m] = fmaf(xv.y, w1, acc[m]);
            acc[m] = fmaf(xv.z, w2, acc[m]);
            acc[m] = fmaf(xv.w, w3, acc[m]);
        }
    }

    int head = col >> 5;
    int lane = col & 31;
    float as = att_src[head * 32 + lane];
    float ad = att_dst[head * 32 + lane];

    #pragma unroll
    for (int m = 0; m < TM; m++) {
        int r = row0 + m;
        if (r < N) {
            g_h[r * F + col] = acc[m];
            float s = acc[m] * as;
            float d = acc[m] * ad;
            #pragma unroll
            for (int o = 16; o > 0; o >>= 1) {
                s += __shfl_xor_sync(0xFFFFFFFFu, s, o);
                d += __shfl_xor_sync(0xFFFFFFFFu, d, o);
            }
            if (lane == 0) {
                g_asrc[r * HEADS + head] = s;
                g_adst[r * HEADS + head] = d;
            }
        }
    }
}

// ---------------------------------------------------------------------------
// Kernel 3: per-edge exp + denom, 4 edges per thread for MLP.
// ---------------------------------------------------------------------------
__device__ __forceinline__ float lrelu(float v) {
    return v > 0.0f ? v : NEG_SLOPE * v;
}

#define ES_EPT 4
__global__ void edge_sum_kernel(const int* __restrict__ ei, int E, int total) {
    int e0 = (blockIdx.x * blockDim.x + threadIdx.x) * ES_EPT;
    if (e0 >= total) return;

    int s[ES_EPT], d[ES_EPT];
    #pragma unroll
    for (int j = 0; j < ES_EPT; j++) {
        int e = e0 + j;
        if (e < E)          { s[j] = ei[e]; d[j] = ei[E + e]; }
        else if (e < total) { s[j] = d[j] = e - E; }
        else                { s[j] = d[j] = -1; }
    }

    float4 as[ES_EPT], ad[ES_EPT];
    #pragma unroll
    for (int j = 0; j < ES_EPT; j++) {
        if (s[j] >= 0) {
            as[j] = __ldg(reinterpret_cast<const float4*>(&g_asrc[s[j] * HEADS]));
            ad[j] = __ldg(reinterpret_cast<const float4*>(&g_adst[d[j] * HEADS]));
        }
    }

    #pragma unroll
    for (int j = 0; j < ES_EPT; j++) {
        if (s[j] >= 0) {
            float4 p;
            p.x = __expf(lrelu(as[j].x + ad[j].x));
            p.y = __expf(lrelu(as[j].y + ad[j].y));
            p.z = __expf(lrelu(as[j].z + ad[j].z));
            p.w = __expf(lrelu(as[j].w + ad[j].w));
            *reinterpret_cast<float4*>(&g_p[(size_t)(e0 + j) * HEADS]) = p;
            float* dst = &g_den[d[j] * HEADS];
            asm volatile("red.global.add.v4.f32 [%0], {%1,%2,%3,%4};"
                         :: "l"(dst), "f"(p.x), "f"(p.y), "f"(p.z), "f"(p.w)
                         : "memory");
        }
    }
}

// ---------------------------------------------------------------------------
// Kernel 4: scatter, 4 edges per WARP (batched for MLP=4 on every load level).
// Lane l handles float4 at feature offset 4l; head = l/8.
// ---------------------------------------------------------------------------
#define SC_EPW 4
__global__ void scatter_kernel(const int* __restrict__ ei,
                               float* __restrict__ out, int E, int total) {
    int warp = (blockIdx.x * blockDim.x + threadIdx.x) >> 5;
    int lane = threadIdx.x & 31;
    int e0 = warp * SC_EPW;
    if (e0 >= total) return;
    int head = lane >> 3;

    int s[SC_EPW], d[SC_EPW];
    #pragma unroll
    for (int j = 0; j < SC_EPW; j++) {
        int e = e0 + j;
        if (e < E)          { s[j] = ei[e]; d[j] = ei[E + e]; }
        else if (e < total) { s[j] = d[j] = e - E; }
        else                { s[j] = d[j] = -1; }
    }

    float pv[SC_EPW], dv[SC_EPW];
    #pragma unroll
    for (int j = 0; j < SC_EPW; j++) {
        if (s[j] >= 0) {
            pv[j] = __ldg(&g_p[(size_t)(e0 + j) * HEADS + head]);
            dv[j] = __ldg(&g_den[d[j] * HEADS + head]);
        }
    }

    float4 hv[SC_EPW];
    #pragma unroll
    for (int j = 0; j < SC_EPW; j++) {
        if (s[j] >= 0) {
            hv[j] = __ldg(reinterpret_cast<const float4*>(&g_h[s[j] * F + lane * 4]));
        }
    }

    #pragma unroll
    for (int j = 0; j < SC_EPW; j++) {
        if (s[j] >= 0) {
            float alpha = pv[j] / (dv[j] + 1e-16f);
            float4 r;
            r.x = hv[j].x * alpha;
            r.y = hv[j].y * alpha;
            r.z = hv[j].z * alpha;
            r.w = hv[j].w * alpha;
            float* dst = &out[d[j] * F + lane * 4];
            asm volatile("red.global.add.v4.f32 [%0], {%1,%2,%3,%4};"
                         :: "l"(dst), "f"(r.x), "f"(r.y), "f"(r.z), "f"(r.w)
                         : "memory");
        }
    }
}

// ---------------------------------------------------------------------------
// Launch
// ---------------------------------------------------------------------------
extern "C" void kernel_launch(void* const* d_in, const int* in_sizes, int n_in,
                              void* d_out, int out_size) {
    const float* x       = (const float*)d_in[0];
    const int*   ei      = (const int*)d_in[1];
    const float* W       = (const float*)d_in[2];
    const float* att_src = (const float*)d_in[3];
    const float* att_dst = (const float*)d_in[4];
    const float* bias    = (const float*)d_in[5];
    float*       out     = (float*)d_out;

    int N = in_sizes[0] / F;
    int E = in_sizes[1] / 2;
    int total = E + N;

    int init_threads = N * (F / 4);
    init_kernel<<<(init_threads + 255) / 256, 256>>>((float4*)out, (const float4*)bias, N);
    proj_kernel<<<(N + 15) / 16, 128>>>(x, W, att_src, att_dst, N);

    int es_threads = (total + ES_EPT - 1) / ES_EPT;
    edge_sum_kernel<<<(es_threads + 255) / 256, 256>>>(ei, E, total);

    long long warps = (total + SC_EPW - 1) / SC_EPW;
    long long sthreads = warps * 32;
    int sblocks = (int)((sthreads + 255) / 256);
    scatter_kernel<<<sblocks, 256>>>(ei, out, E, total);
}

// round 4
// speedup vs baseline: 1.9165x; 1.3577x over previous
#include <cuda_runtime.h>
#include <math.h>

// Fixed problem shape: N=100000, E=1600000, IN_F=128, H=4, C=32.
#define MAXN 100000
#define MAXE 1600000
#define F 128
#define HEADS 4
#define NEG_SLOPE 0.2f
#define SCAN_BLK 1024
#define MAX_NB ((MAXN + SCAN_BLK - 1) / SCAN_BLK)

__device__ __align__(16) float g_h[MAXN * F];          // projected features
__device__ __align__(16) float g_asrc[MAXN * HEADS];   // src attention half
__device__ __align__(16) float g_adst[MAXN * HEADS];   // dst attention half
__device__ int g_cnt[MAXN];                            // in-degree histogram
__device__ int g_off[MAXN + 1];                        // CSR offsets
__device__ int g_cur[MAXN];                            // fill cursors
__device__ int g_bsum[MAX_NB];                         // scan block sums
__device__ int g_bsumex[MAX_NB];                       // scanned block sums
__device__ int g_csr[MAXE];                            // src index per CSR slot

// ---------------------------------------------------------------------------
// Kernel 1: zero histogram
// ---------------------------------------------------------------------------
__global__ void zero_cnt_kernel(int N) {
    int tid = blockIdx.x * blockDim.x + threadIdx.x;
    if (tid < N) g_cnt[tid] = 0;
}

// ---------------------------------------------------------------------------
// Kernel 2: h = x @ W with fused a_src/a_dst epilogue (unchanged).
// ---------------------------------------------------------------------------
__global__ void proj_kernel(const float* __restrict__ x,
                            const float* __restrict__ W,
                            const float* __restrict__ att_src,
                            const float* __restrict__ att_dst,
                            int N) {
    const int TM = 16;
    __shared__ float xs[TM][F];

    int row0 = blockIdx.x * TM;
    int col  = threadIdx.x;

    #pragma unroll
    for (int i = 0; i < TM; i++) {
        int r = row0 + i;
        xs[i][col] = (r < N) ? x[r * F + col] : 0.0f;
    }
    __syncthreads();

    float acc[TM];
    #pragma unroll
    for (int m = 0; m < TM; m++) acc[m] = 0.0f;

    #pragma unroll 8
    for (int k = 0; k < F; k += 4) {
        float w0 = W[(k + 0) * F + col];
        float w1 = W[(k + 1) * F + col];
        float w2 = W[(k + 2) * F + col];
        float w3 = W[(k + 3) * F + col];
        #pragma unroll
        for (int m = 0; m < TM; m++) {
            float4 xv = *reinterpret_cast<const float4*>(&xs[m][k]);
            acc[m] = fmaf(xv.x, w0, acc[m]);
            acc[m] = fmaf(xv.y, w1, acc[m]);
            acc[m] = fmaf(xv.z, w2, acc[m]);
            acc[m] = fmaf(xv.w, w3, acc[m]);
        }
    }

    int head = col >> 5;
    int lane = col & 31;
    float as = att_src[head * 32 + lane];
    float ad = att_dst[head * 32 + lane];

    #pragma unroll
    for (int m = 0; m < TM; m++) {
        int r = row0 + m;
        if (r < N) {
            g_h[r * F + col] = acc[m];
            float s = acc[m] * as;
            float d = acc[m] * ad;
            #pragma unroll
            for (int o = 16; o > 0; o >>= 1) {
                s += __shfl_xor_sync(0xFFFFFFFFu, s, o);
                d += __shfl_xor_sync(0xFFFFFFFFu, d, o);
            }
            if (lane == 0) {
                g_asrc[r * HEADS + head] = s;
                g_adst[r * HEADS + head] = d;
            }
        }
    }
}

// ---------------------------------------------------------------------------
// CSR build: histogram, 3-step scan, fill
// ---------------------------------------------------------------------------
__global__ void hist_kernel(const int* __restrict__ ei, int E) {
    int e = blockIdx.x * blockDim.x + threadIdx.x;
    if (e < E) atomicAdd(&g_cnt[ei[E + e]], 1);
}

__global__ void scan1_kernel(int N) {
    __shared__ int sh[SCAN_BLK];
    int t = threadIdx.x;
    int g = blockIdx.x * SCAN_BLK + t;
    int v = (g < N) ? g_cnt[g] : 0;
    sh[t] = v;
    __syncthreads();
    #pragma unroll
    for (int o = 1; o < SCAN_BLK; o <<= 1) {
        int x = (t >= o) ? sh[t - o] : 0;
        __syncthreads();
        if (t >= o) sh[t] += x;
        __syncthreads();
    }
    if (g < N) g_off[g] = sh[t] - v;   // exclusive within block
    if (t == SCAN_BLK - 1) g_bsum[blockIdx.x] = sh[t];
}

__global__ void scan2_kernel(int NB, int E) {
    // single thread: exclusive scan of <=98 block sums
    if (threadIdx.x == 0 && blockIdx.x == 0) {
        int run = 0;
        for (int i = 0; i < NB; i++) {
            g_bsumex[i] = run;
            run += g_bsum[i];
        }
        g_off[MAXN] = 0;   // unused slot safety
    }
}

__global__ void scan3_kernel(int N, int E) {
    int g = blockIdx.x * blockDim.x + threadIdx.x;
    if (g < N) {
        int v = g_off[g] + g_bsumex[g / SCAN_BLK];
        g_off[g] = v;
        g_cur[g] = v;
    }
    if (g == 0) g_off[N] = E;
}

__global__ void fill_kernel(const int* __restrict__ ei, int E) {
    int e = blockIdx.x * blockDim.x + threadIdx.x;
    if (e < E) {
        int d = ei[E + e];
        int pos = atomicAdd(&g_cur[d], 1);
        g_csr[pos] = ei[e];
    }
}

// ---------------------------------------------------------------------------
// Gather: one warp per dst node. Accumulate sum(p*h[src]) and sum(p) in
// registers over the node's in-edges (plus implicit self-loop), then one
// streaming float4 store. No output atomics.
// ---------------------------------------------------------------------------
__device__ __forceinline__ float lrelu(float v) {
    return v > 0.0f ? v : NEG_SLOPE * v;
}

#define GW 8   // warps per block
__global__ void gather_kernel(float* __restrict__ out,
                              const float* __restrict__ bias, int N) {
    __shared__ int ssrc[GW][32];
    int wip  = threadIdx.x >> 5;
    int warp = blockIdx.x * GW + wip;
    int lane = threadIdx.x & 31;
    if (warp >= N) return;

    int i = warp;
    int head = lane >> 3;
    float ad = g_adst[i * HEADS + head];

    // self-loop seeds the accumulators
    float p0 = __expf(lrelu(g_asrc[i * HEADS + head] + ad));
    float4 hv0 = *reinterpret_cast<const float4*>(&g_h[i * F + lane * 4]);
    float4 acc;
    acc.x = p0 * hv0.x; acc.y = p0 * hv0.y; acc.z = p0 * hv0.z; acc.w = p0 * hv0.w;
    float den = p0;

    int beg = g_off[i];
    int end = g_off[i + 1];

    for (int base = beg; base < end; base += 32) {
        int k = base + lane;
        ssrc[wip][lane] = (k < end) ? g_csr[k] : 0;
        __syncwarp();
        int cnt = end - base;
        if (cnt >= 32) {
            #pragma unroll 8
            for (int j = 0; j < 32; j++) {
                int sj = ssrc[wip][j];
                float p = __expf(lrelu(g_asrc[sj * HEADS + head] + ad));
                float4 hv = *reinterpret_cast<const float4*>(&g_h[sj * F + lane * 4]);
                acc.x = fmaf(p, hv.x, acc.x);
                acc.y = fmaf(p, hv.y, acc.y);
                acc.z = fmaf(p, hv.z, acc.z);
                acc.w = fmaf(p, hv.w, acc.w);
                den += p;
            }
        } else {
            for (int j = 0; j < cnt; j++) {
                int sj = ssrc[wip][j];
                float p = __expf(lrelu(g_asrc[sj * HEADS + head] + ad));
                float4 hv = *reinterpret_cast<const float4*>(&g_h[sj * F + lane * 4]);
                acc.x = fmaf(p, hv.x, acc.x);
                acc.y = fmaf(p, hv.y, acc.y);
                acc.z = fmaf(p, hv.z, acc.z);
                acc.w = fmaf(p, hv.w, acc.w);
                den += p;
            }
        }
        __syncwarp();
    }

    float inv = 1.0f / (den + 1e-16f);
    float4 b = *reinterpret_cast<const float4*>(&bias[lane * 4]);
    float4 r;
    r.x = fmaf(acc.x, inv, b.x);
    r.y = fmaf(acc.y, inv, b.y);
    r.z = fmaf(acc.z, inv, b.z);
    r.w = fmaf(acc.w, inv, b.w);
    *reinterpret_cast<float4*>(&out[i * F + lane * 4]) = r;
}

// ---------------------------------------------------------------------------
// Launch
// ---------------------------------------------------------------------------
extern "C" void kernel_launch(void* const* d_in, const int* in_sizes, int n_in,
                              void* d_out, int out_size) {
    const float* x       = (const float*)d_in[0];
    const int*   ei      = (const int*)d_in[1];
    const float* W       = (const float*)d_in[2];
    const float* att_src = (const float*)d_in[3];
    const float* att_dst = (const float*)d_in[4];
    const float* bias    = (const float*)d_in[5];
    float*       out     = (float*)d_out;

    int N = in_sizes[0] / F;
    int E = in_sizes[1] / 2;
    int NB = (N + SCAN_BLK - 1) / SCAN_BLK;

    zero_cnt_kernel<<<(N + 255) / 256, 256>>>(N);
    proj_kernel<<<(N + 15) / 16, 128>>>(x, W, att_src, att_dst, N);
    hist_kernel<<<(E + 255) / 256, 256>>>(ei, E);
    scan1_kernel<<<NB, SCAN_BLK>>>(N);
    scan2_kernel<<<1, 32>>>(NB, E);
    scan3_kernel<<<(N + 255) / 256, 256>>>(N, E);
    fill_kernel<<<(E + 255) / 256, 256>>>(ei, E);
    gather_kernel<<<(N + GW - 1) / GW, GW * 32>>>(out, bias, N);
}

// round 5
// speedup vs baseline: 2.0236x; 1.0559x over previous
#include <cuda_runtime.h>
#include <cuda_fp16.h>
#include <math.h>

// Fixed problem shape: N=100000, E=1600000, IN_F=128, H=4, C=32.
#define MAXN 100000
#define MAXE 1600000
#define F 128
#define HEADS 4
#define NEG_SLOPE 0.2f
#define SCAN_BLK 1024
#define MAX_NB ((MAXN + SCAN_BLK - 1) / SCAN_BLK)

__device__ __align__(16) __half g_h[MAXN * F];         // projected features (fp16 storage)
__device__ __align__(16) float g_asrc[MAXN * HEADS];   // src attention half
__device__ __align__(16) float g_adst[MAXN * HEADS];   // dst attention half
__device__ int g_cnt[MAXN];
__device__ int g_off[MAXN + 1];
__device__ int g_cur[MAXN];
__device__ int g_bsum[MAX_NB];
__device__ int g_bsumex[MAX_NB];
__device__ int g_csr[MAXE];

// ---------------------------------------------------------------------------
// Packed fp32x2 FMA (sm_103a FFMA2 — only reachable via PTX)
// ---------------------------------------------------------------------------
__device__ __forceinline__ void ffma2(unsigned long long& acc,
                                      unsigned long long a,
                                      unsigned long long b) {
    asm("fma.rn.f32x2 %0, %1, %2, %0;" : "+l"(acc) : "l"(a), "l"(b));
}
__device__ __forceinline__ unsigned long long pack2(float lo, float hi) {
    unsigned long long r;
    asm("mov.b64 %0, {%1, %2};" : "=l"(r) : "f"(lo), "f"(hi));
    return r;
}
__device__ __forceinline__ void unpack2(unsigned long long v, float& lo, float& hi) {
    asm("mov.b64 {%0, %1}, %2;" : "=f"(lo), "=f"(hi) : "l"(v));
}

__global__ void zero_cnt_kernel(int N) {
    int tid = blockIdx.x * blockDim.x + threadIdx.x;
    if (tid < N) g_cnt[tid] = 0;
}

// ---------------------------------------------------------------------------
// proj: h = x @ W via packed f32x2 FMA. 32 rows per block of 128 threads;
// thread owns one output column with 16 row-pair accumulators.
// x tile stored k-major in smem so row pairs load as ld.shared.v2.b64.
// Fused a_src/a_dst epilogue (warp == head).
// ---------------------------------------------------------------------------
#define TM 32
__global__ void proj_kernel(const float* __restrict__ x,
                            const float* __restrict__ W,
                            const float* __restrict__ att_src,
                            const float* __restrict__ att_dst,
                            int N) {
    // row stride 36 floats = 144B: keeps 16B alignment for v2.b64 loads
    __shared__ __align__(16) float xs[F][TM + 4];

    int row0 = blockIdx.x * TM;
    int col  = threadIdx.x;            // 0..127 output column; also k index on load

    #pragma unroll 8
    for (int i = 0; i < TM; i++) {
        int r = row0 + i;
        xs[col][i] = (r < N) ? x[r * F + col] : 0.0f;
    }
    __syncthreads();

    unsigned long long acc[TM / 2];
    #pragma unroll
    for (int m = 0; m < TM / 2; m++) acc[m] = 0ULL;

    #pragma unroll 4
    for (int k = 0; k < F; k++) {
        float w = W[k * F + col];
        unsigned long long wp = pack2(w, w);
        #pragma unroll
        for (int j = 0; j < 8; j++) {
            ulonglong2 xv = *reinterpret_cast<const ulonglong2*>(&xs[k][4 * j]);
            ffma2(acc[2 * j],     xv.x, wp);
            ffma2(acc[2 * j + 1], xv.y, wp);
        }
    }

    int head = col >> 5;
    int lane = col & 31;
    float as = att_src[head * 32 + lane];
    float ad = att_dst[head * 32 + lane];

    #pragma unroll
    for (int m = 0; m < TM / 2; m++) {
        float v0, v1;
        unpack2(acc[m], v0, v1);
        #pragma unroll
        for (int q = 0; q < 2; q++) {
            float v = q ? v1 : v0;
            int r = row0 + 2 * m + q;
            if (r < N) {
                g_h[r * F + col] = __float2half_rn(v);
                float s = v * as;
                float d = v * ad;
                #pragma unroll
                for (int o = 16; o > 0; o >>= 1) {
                    s += __shfl_xor_sync(0xFFFFFFFFu, s, o);
                    d += __shfl_xor_sync(0xFFFFFFFFu, d, o);
                }
                if (lane == 0) {
                    g_asrc[r * HEADS + head] = s;
                    g_adst[r * HEADS + head] = d;
                }
            }
        }
    }
}

// ---------------------------------------------------------------------------
// CSR build: histogram, 3-step scan, fill
// ---------------------------------------------------------------------------
__global__ void hist_kernel(const int* __restrict__ ei, int E) {
    int e = blockIdx.x * blockDim.x + threadIdx.x;
    if (e < E) atomicAdd(&g_cnt[ei[E + e]], 1);
}

__global__ void scan1_kernel(int N) {
    __shared__ int sh[SCAN_BLK];
    int t = threadIdx.x;
    int g = blockIdx.x * SCAN_BLK + t;
    int v = (g < N) ? g_cnt[g] : 0;
    sh[t] = v;
    __syncthreads();
    #pragma unroll
    for (int o = 1; o < SCAN_BLK; o <<= 1) {
        int xv = (t >= o) ? sh[t - o] : 0;
        __syncthreads();
        if (t >= o) sh[t] += xv;
        __syncthreads();
    }
    if (g < N) g_off[g] = sh[t] - v;
    if (t == SCAN_BLK - 1) g_bsum[blockIdx.x] = sh[t];
}

__global__ void scan2_kernel(int NB) {
    if (threadIdx.x == 0 && blockIdx.x == 0) {
        int run = 0;
        for (int i = 0; i < NB; i++) {
            g_bsumex[i] = run;
            run += g_bsum[i];
        }
    }
}

__global__ void scan3_kernel(int N, int E) {
    int g = blockIdx.x * blockDim.x + threadIdx.x;
    if (g < N) {
        int v = g_off[g] + g_bsumex[g / SCAN_BLK];
        g_off[g] = v;
        g_cur[g] = v;
    }
    if (g == 0) g_off[N] = E;
}

__global__ void fill_kernel(const int* __restrict__ ei, int E) {
    int e = blockIdx.x * blockDim.x + threadIdx.x;
    if (e < E) {
        int d = ei[E + e];
        int pos = atomicAdd(&g_cur[d], 1);
        g_csr[pos] = ei[e];
    }
}

// ---------------------------------------------------------------------------
// Gather: warp per dst node; fp16 h gathers (8B/lane), fp32 accumulation.
// ---------------------------------------------------------------------------
__device__ __forceinline__ float lrelu(float v) {
    return v > 0.0f ? v : NEG_SLOPE * v;
}

__device__ __forceinline__ void acc_h16(float4& acc, float p, const __half* hp) {
    unsigned long long u = *reinterpret_cast<const unsigned long long*>(hp);
    __half2 h01 = reinterpret_cast<__half2*>(&u)[0];
    __half2 h23 = reinterpret_cast<__half2*>(&u)[1];
    float2 f01 = __half22float2(h01);
    float2 f23 = __half22float2(h23);
    acc.x = fmaf(p, f01.x, acc.x);
    acc.y = fmaf(p, f01.y, acc.y);
    acc.z = fmaf(p, f23.x, acc.z);
    acc.w = fmaf(p, f23.y, acc.w);
}

#define GW 8
__global__ void gather_kernel(float* __restrict__ out,
                              const float* __restrict__ bias, int N) {
    __shared__ int ssrc[GW][32];
    int wip  = threadIdx.x >> 5;
    int i    = blockIdx.x * GW + wip;
    int lane = threadIdx.x & 31;
    if (i >= N) return;

    int head = lane >> 3;
    float ad = g_adst[i * HEADS + head];

    float p0 = __expf(lrelu(g_asrc[i * HEADS + head] + ad));
    float4 acc = make_float4(0.f, 0.f, 0.f, 0.f);
    acc_h16(acc, p0, &g_h[(size_t)i * F + lane * 4]);
    float den = p0;

    int beg = g_off[i];
    int end = g_off[i + 1];

    for (int base = beg; base < end; base += 32) {
        int k = base + lane;
        ssrc[wip][lane] = (k < end) ? g_csr[k] : 0;
        __syncwarp();
        int cnt = end - base;
        if (cnt >= 32) {
            #pragma unroll 8
            for (int j = 0; j < 32; j++) {
                int sj = ssrc[wip][j];
                float p = __expf(lrelu(g_asrc[sj * HEADS + head] + ad));
                acc_h16(acc, p, &g_h[(size_t)sj * F + lane * 4]);
                den += p;
            }
        } else {
            for (int j = 0; j < cnt; j++) {
                int sj = ssrc[wip][j];
                float p = __expf(lrelu(g_asrc[sj * HEADS + head] + ad));
                acc_h16(acc, p, &g_h[(size_t)sj * F + lane * 4]);
                den += p;
            }
        }
        __syncwarp();
    }

    float inv = 1.0f / (den + 1e-16f);
    float4 b = *reinterpret_cast<const float4*>(&bias[lane * 4]);
    float4 r;
    r.x = fmaf(acc.x, inv, b.x);
    r.y = fmaf(acc.y, inv, b.y);
    r.z = fmaf(acc.z, inv, b.z);
    r.w = fmaf(acc.w, inv, b.w);
    *reinterpret_cast<float4*>(&out[i * F + lane * 4]) = r;
}

// ---------------------------------------------------------------------------
// Launch
// ---------------------------------------------------------------------------
extern "C" void kernel_launch(void* const* d_in, const int* in_sizes, int n_in,
                              void* d_out, int out_size) {
    const float* x       = (const float*)d_in[0];
    const int*   ei      = (const int*)d_in[1];
    const float* W       = (const float*)d_in[2];
    const float* att_src = (const float*)d_in[3];
    const float* att_dst = (const float*)d_in[4];
    const float* bias    = (const float*)d_in[5];
    float*       out     = (float*)d_out;

    int N = in_sizes[0] / F;
    int E = in_sizes[1] / 2;
    int NB = (N + SCAN_BLK - 1) / SCAN_BLK;

    zero_cnt_kernel<<<(N + 255) / 256, 256>>>(N);
    proj_kernel<<<(N + TM - 1) / TM, 128>>>(x, W, att_src, att_dst, N);
    hist_kernel<<<(E + 255) / 256, 256>>>(ei, E);
    scan1_kernel<<<NB, SCAN_BLK>>>(N);
    scan2_kernel<<<1, 32>>>(NB);
    scan3_kernel<<<(N + 255) / 256, 256>>>(N, E);
    fill_kernel<<<(E + 255) / 256, 256>>>(ei, E);
    gather_kernel<<<(N + GW - 1) / GW, GW * 32>>>(out, bias, N);
}

// round 6
// speedup vs baseline: 2.5551x; 1.2627x over previous
#include <cuda_runtime.h>
#include <cuda_fp16.h>
#include <math.h>

// Fixed problem shape: N=100000, E=1600000, IN_F=128, H=4, C=32.
#define MAXN 100000
#define MAXE 1600000
#define F 128
#define HEADS 4
#define NEG_SLOPE 0.2f
#define SCAN_BLK 1024
#define MAX_NB ((MAXN + SCAN_BLK - 1) / SCAN_BLK)

typedef unsigned long long u64;

__device__ __align__(16) __half g_h[MAXN * F];         // projected features (fp16 storage)
__device__ __align__(16) float g_asrc[MAXN * HEADS];
__device__ __align__(16) float g_adst[MAXN * HEADS];
__device__ __align__(16) float g_wr[F * F];            // rearranged W: [k][lane*4+head]
__device__ int g_cnt[MAXN];
__device__ int g_off[MAXN + 1];
__device__ int g_cur[MAXN];
__device__ int g_bsum[MAX_NB];
__device__ int g_bsumex[MAX_NB];
__device__ int g_csr[MAXE];

// ---------------------------------------------------------------------------
// packed f32x2 helpers (FFMA2 path, PTX-only on sm_103a)
// ---------------------------------------------------------------------------
__device__ __forceinline__ void ffma2(u64& acc, u64 a, u64 b) {
    asm("fma.rn.f32x2 %0, %1, %2, %0;" : "+l"(acc) : "l"(a), "l"(b));
}
__device__ __forceinline__ u64 mulf2(u64 a, u64 b) {
    u64 r; asm("mul.rn.f32x2 %0, %1, %2;" : "=l"(r) : "l"(a), "l"(b)); return r;
}
__device__ __forceinline__ u64 addf2(u64 a, u64 b) {
    u64 r; asm("add.rn.f32x2 %0, %1, %2;" : "=l"(r) : "l"(a), "l"(b)); return r;
}
__device__ __forceinline__ u64 pack2(float lo, float hi) {
    u64 r; asm("mov.b64 %0, {%1, %2};" : "=l"(r) : "f"(lo), "f"(hi)); return r;
}
__device__ __forceinline__ void unpack2(u64 v, float& lo, float& hi) {
    asm("mov.b64 {%0, %1}, %2;" : "=f"(lo), "=f"(hi) : "l"(v));
}

__global__ void zero_cnt_kernel(int N) {
    int tid = blockIdx.x * blockDim.x + threadIdx.x;
    if (tid < N) g_cnt[tid] = 0;
}

// W rearrange: g_wr[k][l*4+h] = W[k][h*32+l]
__global__ void wr_kernel(const float* __restrict__ W) {
    int tid = blockIdx.x * blockDim.x + threadIdx.x;
    if (tid < F * F) {
        int k = tid >> 7, c = tid & 127;
        int l = c >> 2, h = c & 3;
        g_wr[tid] = W[k * F + h * 32 + l];
    }
}

// ---------------------------------------------------------------------------
// proj: 32 rows x 128 cols per block (128 threads). Warp w -> rows [8w,8w+8).
// Lane l -> cols {l, 32+l, 64+l, 96+l} (col group c == head c).
// Per k: 16 FFMA2 + 4 LDS.64 (broadcast) + 1 LDG.128 (g_wr, L1-hot).
// ---------------------------------------------------------------------------
#define TM 32
#define XS_STRIDE 34
__global__ void proj_kernel(const float* __restrict__ x,
                            const float* __restrict__ att_src,
                            const float* __restrict__ att_dst,
                            int N) {
    __shared__ __align__(16) float xs[F * XS_STRIDE];   // [k][row], stride 34

    int row0 = blockIdx.x * TM;
    int t    = threadIdx.x;          // 0..127
    int w    = t >> 5;               // warp -> row slice
    int lane = t & 31;

    // load x tile: iteration i reads row row0+i coalesced over t(=k)
    #pragma unroll 8
    for (int i = 0; i < TM; i++) {
        int r = row0 + i;
        xs[t * XS_STRIDE + i] = (r < N) ? x[r * F + t] : 0.0f;
    }
    __syncthreads();

    u64 acc[4][4];                   // [col-group/head][row-pair]
    #pragma unroll
    for (int c = 0; c < 4; c++)
        #pragma unroll
        for (int j = 0; j < 4; j++) acc[c][j] = 0ULL;

    const float* wrp = &g_wr[lane * 4];
    #pragma unroll 4
    for (int k = 0; k < F; k++) {
        float4 wv = *reinterpret_cast<const float4*>(&wrp[k * F]);
        u64 wp0 = pack2(wv.x, wv.x);
        u64 wp1 = pack2(wv.y, wv.y);
        u64 wp2 = pack2(wv.z, wv.z);
        u64 wp3 = pack2(wv.w, wv.w);
        const float* xk = &xs[k * XS_STRIDE + 8 * w];
        u64 x0 = *reinterpret_cast<const u64*>(xk + 0);
        u64 x1 = *reinterpret_cast<const u64*>(xk + 2);
        u64 x2 = *reinterpret_cast<const u64*>(xk + 4);
        u64 x3 = *reinterpret_cast<const u64*>(xk + 6);
        ffma2(acc[0][0], x0, wp0); ffma2(acc[0][1], x1, wp0);
        ffma2(acc[0][2], x2, wp0); ffma2(acc[0][3], x3, wp0);
        ffma2(acc[1][0], x0, wp1); ffma2(acc[1][1], x1, wp1);
        ffma2(acc[1][2], x2, wp1); ffma2(acc[1][3], x3, wp1);
        ffma2(acc[2][0], x0, wp2); ffma2(acc[2][1], x1, wp2);
        ffma2(acc[2][2], x2, wp2); ffma2(acc[2][3], x3, wp2);
        ffma2(acc[3][0], x0, wp3); ffma2(acc[3][1], x1, wp3);
        ffma2(acc[3][2], x2, wp3); ffma2(acc[3][3], x3, wp3);
    }

    // epilogue: store fp16 h, reduce a_src/a_dst per (row, head)
    #pragma unroll
    for (int c = 0; c < 4; c++) {
        float as = att_src[c * 32 + lane];
        float ad = att_dst[c * 32 + lane];
        u64 as2 = pack2(as, as);
        u64 ad2 = pack2(ad, ad);
        #pragma unroll
        for (int j = 0; j < 4; j++) {
            int r = row0 + 8 * w + 2 * j;       // rows r, r+1
            float v0, v1;
            unpack2(acc[c][j], v0, v1);
            if (r < N)     g_h[(size_t)r * F + c * 32 + lane]       = __float2half_rn(v0);
            if (r + 1 < N) g_h[(size_t)(r + 1) * F + c * 32 + lane] = __float2half_rn(v1);

            u64 s = mulf2(acc[c][j], as2);
            u64 d = mulf2(acc[c][j], ad2);
            #pragma unroll
            for (int o = 16; o > 0; o >>= 1) {
                s = addf2(s, __shfl_xor_sync(0xFFFFFFFFu, s, o));
                d = addf2(d, __shfl_xor_sync(0xFFFFFFFFu, d, o));
            }
            if (lane == 0) {
                float s0, s1, d0, d1;
                unpack2(s, s0, s1);
                unpack2(d, d0, d1);
                if (r < N)     { g_asrc[r * HEADS + c] = s0;       g_adst[r * HEADS + c] = d0; }
                if (r + 1 < N) { g_asrc[(r + 1) * HEADS + c] = s1; g_adst[(r + 1) * HEADS + c] = d1; }
            }
        }
    }
}

// ---------------------------------------------------------------------------
// CSR build
// ---------------------------------------------------------------------------
__global__ void hist_kernel(const int* __restrict__ ei, int E) {
    int e = blockIdx.x * blockDim.x + threadIdx.x;
    if (e < E) atomicAdd(&g_cnt[ei[E + e]], 1);
}

__global__ void scan1_kernel(int N) {
    __shared__ int sh[SCAN_BLK];
    int t = threadIdx.x;
    int g = blockIdx.x * SCAN_BLK + t;
    int v = (g < N) ? g_cnt[g] : 0;
    sh[t] = v;
    __syncthreads();
    #pragma unroll
    for (int o = 1; o < SCAN_BLK; o <<= 1) {
        int xv = (t >= o) ? sh[t - o] : 0;
        __syncthreads();
        if (t >= o) sh[t] += xv;
        __syncthreads();
    }
    if (g < N) g_off[g] = sh[t] - v;
    if (t == SCAN_BLK - 1) g_bsum[blockIdx.x] = sh[t];
}

__global__ void scan2_kernel(int NB) {
    if (threadIdx.x == 0 && blockIdx.x == 0) {
        int run = 0;
        for (int i = 0; i < NB; i++) { g_bsumex[i] = run; run += g_bsum[i]; }
    }
}

__global__ void scan3_kernel(int N, int E) {
    int g = blockIdx.x * blockDim.x + threadIdx.x;
    if (g < N) {
        int v = g_off[g] + g_bsumex[g / SCAN_BLK];
        g_off[g] = v;
        g_cur[g] = v;
    }
    if (g == 0) g_off[N] = E;
}

__global__ void fill_kernel(const int* __restrict__ ei, int E) {
    int e = blockIdx.x * blockDim.x + threadIdx.x;
    if (e < E) {
        int d = ei[E + e];
        int pos = atomicAdd(&g_cur[d], 1);
        g_csr[pos] = ei[e];
    }
}

// ---------------------------------------------------------------------------
// Gather: warp per dst. Lane-parallel phase loads 32 srcs + computes all-head
// p into smem; serial j-loop is LDS(p) + LDG.64(h) + FMAs only.
// ---------------------------------------------------------------------------
__device__ __forceinline__ float lrelu(float v) {
    return v > 0.0f ? v : NEG_SLOPE * v;
}
__device__ __forceinline__ void acc_h16(float4& acc, float p, const __half* hp) {
    u64 u = *reinterpret_cast<const u64*>(hp);
    __half2 h01 = reinterpret_cast<__half2*>(&u)[0];
    __half2 h23 = reinterpret_cast<__half2*>(&u)[1];
    float2 f01 = __half22float2(h01);
    float2 f23 = __half22float2(h23);
    acc.x = fmaf(p, f01.x, acc.x);
    acc.y = fmaf(p, f01.y, acc.y);
    acc.z = fmaf(p, f23.x, acc.z);
    acc.w = fmaf(p, f23.y, acc.w);
}

#define GW 8
__global__ void gather_kernel(float* __restrict__ out,
                              const float* __restrict__ bias, int N) {
    __shared__ int    ssrc[GW][32];
    __shared__ float4 sp[GW][32];
    int wip  = threadIdx.x >> 5;
    int i    = blockIdx.x * GW + wip;
    int lane = threadIdx.x & 31;
    if (i >= N) return;

    int head = lane >> 3;
    float4 adv = *reinterpret_cast<const float4*>(&g_adst[i * HEADS]);
    float ad_h = (head == 0) ? adv.x : (head == 1) ? adv.y : (head == 2) ? adv.z : adv.w;

    // self-loop
    float p0 = __expf(lrelu(g_asrc[i * HEADS + head] + ad_h));
    float4 acc = make_float4(0.f, 0.f, 0.f, 0.f);
    acc_h16(acc, p0, &g_h[(size_t)i * F + lane * 4]);
    float den = p0;

    int beg = g_off[i];
    int end = g_off[i + 1];

    for (int base = beg; base < end; base += 32) {
        int k = base + lane;
        int sj = (k < end) ? g_csr[k] : 0;
        ssrc[wip][lane] = sj;
        float4 a = *reinterpret_cast<const float4*>(&g_asrc[sj * HEADS]);
        float4 p4;
        p4.x = __expf(lrelu(a.x + adv.x));
        p4.y = __expf(lrelu(a.y + adv.y));
        p4.z = __expf(lrelu(a.z + adv.z));
        p4.w = __expf(lrelu(a.w + adv.w));
        sp[wip][lane] = p4;
        __syncwarp();

        int cnt = end - base;
        if (cnt >= 32) {
            #pragma unroll 8
            for (int j = 0; j < 32; j++) {
                int s = ssrc[wip][j];
                float p = reinterpret_cast<const float*>(&sp[wip][j])[head];
                acc_h16(acc, p, &g_h[(size_t)s * F + lane * 4]);
                den += p;
            }
        } else {
            for (int j = 0; j < cnt; j++) {
                int s = ssrc[wip][j];
                float p = reinterpret_cast<const float*>(&sp[wip][j])[head];
                acc_h16(acc, p, &g_h[(size_t)s * F + lane * 4]);
                den += p;
            }
        }
        __syncwarp();
    }

    float inv = 1.0f / (den + 1e-16f);
    float4 b = *reinterpret_cast<const float4*>(&bias[lane * 4]);
    float4 r;
    r.x = fmaf(acc.x, inv, b.x);
    r.y = fmaf(acc.y, inv, b.y);
    r.z = fmaf(acc.z, inv, b.z);
    r.w = fmaf(acc.w, inv, b.w);
    *reinterpret_cast<float4*>(&out[i * F + lane * 4]) = r;
}

// ---------------------------------------------------------------------------
// Launch (proj placed at launch index 3 = ncu's profiled slot)
// ---------------------------------------------------------------------------
extern "C" void kernel_launch(void* const* d_in, const int* in_sizes, int n_in,
                              void* d_out, int out_size) {
    const float* x       = (const float*)d_in[0];
    const int*   ei      = (const int*)d_in[1];
    const float* W       = (const float*)d_in[2];
    const float* att_src = (const float*)d_in[3];
    const float* att_dst = (const float*)d_in[4];
    const float* bias    = (const float*)d_in[5];
    float*       out     = (float*)d_out;

    int N = in_sizes[0] / F;
    int E = in_sizes[1] / 2;
    int NB = (N + SCAN_BLK - 1) / SCAN_BLK;

    zero_cnt_kernel<<<(N + 255) / 256, 256>>>(N);                 // 0
    wr_kernel<<<(F * F + 255) / 256, 256>>>(W);                   // 1
    hist_kernel<<<(E + 255) / 256, 256>>>(ei, E);                 // 2
    proj_kernel<<<(N + TM - 1) / TM, 128>>>(x, att_src, att_dst, N); // 3 (profiled)
    scan1_kernel<<<NB, SCAN_BLK>>>(N);                            // 4
    scan2_kernel<<<1, 32>>>(NB);                                  // 5
    scan3_kernel<<<(N + 255) / 256, 256>>>(N, E);                 // 6
    fill_kernel<<<(E + 255) / 256, 256>>>(ei, E);                 // 7
    gather_kernel<<<(N + GW - 1) / GW, GW * 32>>>(out, bias, N);  // 8
}

// round 7
// speedup vs baseline: 2.6238x; 1.0269x over previous
#include <cuda_runtime.h>
#include <cuda_fp16.h>
#include <math.h>

// Fixed problem shape: N=100000, E=1600000, IN_F=128, H=4, C=32.
#define MAXN 100000
#define MAXE 1600000
#define F 128
#define HEADS 4
#define NEG_SLOPE 0.2f
#define SCAN_BLK 1024
#define MAX_NB ((MAXN + SCAN_BLK - 1) / SCAN_BLK)

typedef unsigned long long u64;

__device__ __align__(16) __half g_h[MAXN * F];         // projected features (fp16)
__device__ __align__(16) float g_asrc[MAXN * HEADS];
__device__ __align__(16) float g_adst[MAXN * HEADS];
__device__ __align__(16) float g_wr[F * F];            // rearranged W: [k][lane*4+head]
__device__ int g_cnt[MAXN];
__device__ int g_off[MAXN + 1];
__device__ int g_cur[MAXN];
__device__ int g_bsum[MAX_NB];
__device__ int g_bsumex[MAX_NB];
__device__ int g_csr[MAXE];

// ---------------------------------------------------------------------------
// packed f32x2 helpers
// ---------------------------------------------------------------------------
__device__ __forceinline__ void ffma2(u64& acc, u64 a, u64 b) {
    asm("fma.rn.f32x2 %0, %1, %2, %0;" : "+l"(acc) : "l"(a), "l"(b));
}
__device__ __forceinline__ u64 pack2(float lo, float hi) {
    u64 r; asm("mov.b64 %0, {%1, %2};" : "=l"(r) : "f"(lo), "f"(hi)); return r;
}
__device__ __forceinline__ void unpack2(u64 v, float& lo, float& hi) {
    asm("mov.b64 {%0, %1}, %2;" : "=f"(lo), "=f"(hi) : "l"(v));
}

// ---------------------------------------------------------------------------
// setup: zero histogram + rearrange W (merged)
// ---------------------------------------------------------------------------
__global__ void setup_kernel(const float* __restrict__ W, int N) {
    int tid = blockIdx.x * blockDim.x + threadIdx.x;
    if (tid < N) g_cnt[tid] = 0;
    if (tid < F * F) {
        int k = tid >> 7, c = tid & 127;
        int l = c >> 2, h = c & 3;
        g_wr[tid] = W[k * F + h * 32 + l];
    }
}

// ---------------------------------------------------------------------------
// proj: 32 rows x 128 cols per block (128 threads). Warp w -> rows [8w,8w+8).
// Lane l -> cols {l, 32+l, 64+l, 96+l}. Pure GEMM; no reduction epilogue.
// ---------------------------------------------------------------------------
#define TM 32
#define XS_STRIDE 34
__global__ void proj_kernel(const float* __restrict__ x, int N) {
    __shared__ __align__(16) float xs[F * XS_STRIDE];

    int row0 = blockIdx.x * TM;
    int t    = threadIdx.x;
    int w    = t >> 5;
    int lane = t & 31;

    #pragma unroll 8
    for (int i = 0; i < TM; i++) {
        int r = row0 + i;
        xs[t * XS_STRIDE + i] = (r < N) ? x[r * F + t] : 0.0f;
    }
    __syncthreads();

    u64 acc[4][4];
    #pragma unroll
    for (int c = 0; c < 4; c++)
        #pragma unroll
        for (int j = 0; j < 4; j++) acc[c][j] = 0ULL;

    const float* wrp = &g_wr[lane * 4];
    #pragma unroll 4
    for (int k = 0; k < F; k++) {
        float4 wv = *reinterpret_cast<const float4*>(&wrp[k * F]);
        u64 wp0 = pack2(wv.x, wv.x);
        u64 wp1 = pack2(wv.y, wv.y);
        u64 wp2 = pack2(wv.z, wv.z);
        u64 wp3 = pack2(wv.w, wv.w);
        const float* xk = &xs[k * XS_STRIDE + 8 * w];
        u64 x0 = *reinterpret_cast<const u64*>(xk + 0);
        u64 x1 = *reinterpret_cast<const u64*>(xk + 2);
        u64 x2 = *reinterpret_cast<const u64*>(xk + 4);
        u64 x3 = *reinterpret_cast<const u64*>(xk + 6);
        ffma2(acc[0][0], x0, wp0); ffma2(acc[0][1], x1, wp0);
        ffma2(acc[0][2], x2, wp0); ffma2(acc[0][3], x3, wp0);
        ffma2(acc[1][0], x0, wp1); ffma2(acc[1][1], x1, wp1);
        ffma2(acc[1][2], x2, wp1); ffma2(acc[1][3], x3, wp1);
        ffma2(acc[2][0], x0, wp2); ffma2(acc[2][1], x1, wp2);
        ffma2(acc[2][2], x2, wp2); ffma2(acc[2][3], x3, wp2);
        ffma2(acc[3][0], x0, wp3); ffma2(acc[3][1], x1, wp3);
        ffma2(acc[3][2], x2, wp3); ffma2(acc[3][3], x3, wp3);
    }

    #pragma unroll
    for (int c = 0; c < 4; c++) {
        #pragma unroll
        for (int j = 0; j < 4; j++) {
            int r = row0 + 8 * w + 2 * j;
            float v0, v1;
            unpack2(acc[c][j], v0, v1);
            if (r < N)     g_h[(size_t)r * F + c * 32 + lane]       = __float2half_rn(v0);
            if (r + 1 < N) g_h[(size_t)(r + 1) * F + c * 32 + lane] = __float2half_rn(v1);
        }
    }
}

// ---------------------------------------------------------------------------
// asrc: a_src/a_dst from fp16 h. Warp handles 4 rows; lane covers 4 features
// (head = lane>>3); 3-level segmented shuffle reduce within 8-lane head group.
// ---------------------------------------------------------------------------
#define AR 4
__global__ void asrc_kernel(const float* __restrict__ att_src,
                            const float* __restrict__ att_dst, int N) {
    int gw   = (blockIdx.x * blockDim.x + threadIdx.x) >> 5;
    int lane = threadIdx.x & 31;
    int row0 = gw * AR;
    if (row0 >= N) return;

    int head  = lane >> 3;
    int cbase = (lane & 7) * 4;
    float4 as = *reinterpret_cast<const float4*>(&att_src[head * 32 + cbase]);
    float4 ad = *reinterpret_cast<const float4*>(&att_dst[head * 32 + cbase]);

    u64 u[AR];
    #pragma unroll
    for (int i = 0; i < AR; i++) {
        int r = row0 + i;
        u[i] = (r < N) ? *reinterpret_cast<const u64*>(&g_h[(size_t)r * F + lane * 4]) : 0ULL;
    }

    #pragma unroll
    for (int i = 0; i < AR; i++) {
        int r = row0 + i;
        if (r >= N) break;
        float2 f01 = __half22float2(reinterpret_cast<__half2*>(&u[i])[0]);
        float2 f23 = __half22float2(reinterpret_cast<__half2*>(&u[i])[1]);
        float s = f01.x * as.x + f01.y * as.y + f23.x * as.z + f23.y * as.w;
        float d = f01.x * ad.x + f01.y * ad.y + f23.x * ad.z + f23.y * ad.w;
        #pragma unroll
        for (int o = 4; o > 0; o >>= 1) {
            s += __shfl_xor_sync(0xFFFFFFFFu, s, o);
            d += __shfl_xor_sync(0xFFFFFFFFu, d, o);
        }
        if ((lane & 7) == 0) {
            g_asrc[r * HEADS + head] = s;
            g_adst[r * HEADS + head] = d;
        }
    }
}

// ---------------------------------------------------------------------------
// CSR build
// ---------------------------------------------------------------------------
__global__ void hist_kernel(const int* __restrict__ ei, int E) {
    int e = blockIdx.x * blockDim.x + threadIdx.x;
    if (e < E) atomicAdd(&g_cnt[ei[E + e]], 1);
}

__global__ void scan1_kernel(int N) {
    __shared__ int sh[SCAN_BLK];
    int t = threadIdx.x;
    int g = blockIdx.x * SCAN_BLK + t;
    int v = (g < N) ? g_cnt[g] : 0;
    sh[t] = v;
    __syncthreads();
    #pragma unroll
    for (int o = 1; o < SCAN_BLK; o <<= 1) {
        int xv = (t >= o) ? sh[t - o] : 0;
        __syncthreads();
        if (t >= o) sh[t] += xv;
        __syncthreads();
    }
    if (g < N) g_off[g] = sh[t] - v;
    if (t == SCAN_BLK - 1) g_bsum[blockIdx.x] = sh[t];
}

__global__ void scan2_kernel(int NB) {
    if (threadIdx.x == 0 && blockIdx.x == 0) {
        int run = 0;
        for (int i = 0; i < NB; i++) { g_bsumex[i] = run; run += g_bsum[i]; }
    }
}

__global__ void scan3_kernel(int N, int E) {
    int g = blockIdx.x * blockDim.x + threadIdx.x;
    if (g < N) {
        int v = g_off[g] + g_bsumex[g / SCAN_BLK];
        g_off[g] = v;
        g_cur[g] = v;
    }
    if (g == 0) g_off[N] = E;
}

__global__ void fill_kernel(const int* __restrict__ ei, int E) {
    int e = blockIdx.x * blockDim.x + threadIdx.x;
    if (e < E) {
        int d = ei[E + e];
        int pos = atomicAdd(&g_cur[d], 1);
        g_csr[pos] = ei[e];
    }
}

// ---------------------------------------------------------------------------
// Gather (unchanged from R6)
// ---------------------------------------------------------------------------
__device__ __forceinline__ float lrelu(float v) {
    return v > 0.0f ? v : NEG_SLOPE * v;
}
__device__ __forceinline__ void acc_h16(float4& acc, float p, const __half* hp) {
    u64 u = *reinterpret_cast<const u64*>(hp);
    __half2 h01 = reinterpret_cast<__half2*>(&u)[0];
    __half2 h23 = reinterpret_cast<__half2*>(&u)[1];
    float2 f01 = __half22float2(h01);
    float2 f23 = __half22float2(h23);
    acc.x = fmaf(p, f01.x, acc.x);
    acc.y = fmaf(p, f01.y, acc.y);
    acc.z = fmaf(p, f23.x, acc.z);
    acc.w = fmaf(p, f23.y, acc.w);
}

#define GW 8
__global__ void gather_kernel(float* __restrict__ out,
                              const float* __restrict__ bias, int N) {
    __shared__ int    ssrc[GW][32];
    __shared__ float4 sp[GW][32];
    int wip  = threadIdx.x >> 5;
    int i    = blockIdx.x * GW + wip;
    int lane = threadIdx.x & 31;
    if (i >= N) return;

    int head = lane >> 3;
    float4 adv = *reinterpret_cast<const float4*>(&g_adst[i * HEADS]);
    float ad_h = (head == 0) ? adv.x : (head == 1) ? adv.y : (head == 2) ? adv.z : adv.w;

    float p0 = __expf(lrelu(g_asrc[i * HEADS + head] + ad_h));
    float4 acc = make_float4(0.f, 0.f, 0.f, 0.f);
    acc_h16(acc, p0, &g_h[(size_t)i * F + lane * 4]);
    float den = p0;

    int beg = g_off[i];
    int end = g_off[i + 1];

    for (int base = beg; base < end; base += 32) {
        int k = base + lane;
        int sj = (k < end) ? g_csr[k] : 0;
        ssrc[wip][lane] = sj;
        float4 a = *reinterpret_cast<const float4*>(&g_asrc[sj * HEADS]);
        float4 p4;
        p4.x = __expf(lrelu(a.x + adv.x));
        p4.y = __expf(lrelu(a.y + adv.y));
        p4.z = __expf(lrelu(a.z + adv.z));
        p4.w = __expf(lrelu(a.w + adv.w));
        sp[wip][lane] = p4;
        __syncwarp();

        int cnt = end - base;
        if (cnt >= 32) {
            #pragma unroll 8
            for (int j = 0; j < 32; j++) {
                int s = ssrc[wip][j];
                float p = reinterpret_cast<const float*>(&sp[wip][j])[head];
                acc_h16(acc, p, &g_h[(size_t)s * F + lane * 4]);
                den += p;
            }
        } else {
            for (int j = 0; j < cnt; j++) {
                int s = ssrc[wip][j];
                float p = reinterpret_cast<const float*>(&sp[wip][j])[head];
                acc_h16(acc, p, &g_h[(size_t)s * F + lane * 4]);
                den += p;
            }
        }
        __syncwarp();
    }

    float inv = 1.0f / (den + 1e-16f);
    float4 b = *reinterpret_cast<const float4*>(&bias[lane * 4]);
    float4 r;
    r.x = fmaf(acc.x, inv, b.x);
    r.y = fmaf(acc.y, inv, b.y);
    r.z = fmaf(acc.z, inv, b.z);
    r.w = fmaf(acc.w, inv, b.w);
    *reinterpret_cast<float4*>(&out[i * F + lane * 4]) = r;
}

// ---------------------------------------------------------------------------
// Launch (proj kept at index 3 = ncu's profiled slot)
// ---------------------------------------------------------------------------
extern "C" void kernel_launch(void* const* d_in, const int* in_sizes, int n_in,
                              void* d_out, int out_size) {
    const float* x       = (const float*)d_in[0];
    const int*   ei      = (const int*)d_in[1];
    const float* W       = (const float*)d_in[2];
    const float* att_src = (const float*)d_in[3];
    const float* att_dst = (const float*)d_in[4];
    const float* bias    = (const float*)d_in[5];
    float*       out     = (float*)d_out;

    int N = in_sizes[0] / F;
    int E = in_sizes[1] / 2;
    int NB = (N + SCAN_BLK - 1) / SCAN_BLK;

    setup_kernel<<<(N + 255) / 256, 256>>>(W, N);                 // 0
    hist_kernel<<<(E + 255) / 256, 256>>>(ei, E);                 // 1
    scan1_kernel<<<NB, SCAN_BLK>>>(N);                            // 2
    proj_kernel<<<(N + TM - 1) / TM, 128>>>(x, N);                // 3 (profiled)
    scan2_kernel<<<1, 32>>>(NB);                                  // 4
    scan3_kernel<<<(N + 255) / 256, 256>>>(N, E);                 // 5
    fill_kernel<<<(E + 255) / 256, 256>>>(ei, E);                 // 6
    int awarps = (N + AR - 1) / AR;
    asrc_kernel<<<(awarps * 32 + 255) / 256, 256>>>(att_src, att_dst, N); // 7
    gather_kernel<<<(N + GW - 1) / GW, GW * 32>>>(out, bias, N);  // 8
}

// round 8
// speedup vs baseline: 2.6274x; 1.0014x over previous
#include <cuda_runtime.h>
#include <cuda_fp16.h>
#include <mma.h>
#include <math.h>

using namespace nvcuda;

// Fixed problem shape: N=100000, E=1600000, IN_F=128, H=4, C=32.
#define MAXN 100000
#define MAXE 1600000
#define F 128
#define HEADS 4
#define NEG_SLOPE 0.2f
#define SCAN_BLK 1024
#define MAX_NB ((MAXN + SCAN_BLK - 1) / SCAN_BLK)

typedef unsigned long long u64;

__device__ __align__(16) __half g_h[MAXN * F];         // projected features (fp16)
__device__ __align__(16) __half g_wh[F * F];           // W in fp16, natural [k][n]
__device__ __align__(16) float g_asrc[MAXN * HEADS];
__device__ __align__(16) float g_adst[MAXN * HEADS];
__device__ int g_cnt[MAXN];
__device__ int g_off[MAXN + 1];
__device__ int g_cur[MAXN];
__device__ int g_bsum[MAX_NB];
__device__ int g_bsumex[MAX_NB];
__device__ int g_csr[MAXE];

// ---------------------------------------------------------------------------
// setup: zero histogram + convert W to fp16
// ---------------------------------------------------------------------------
__global__ void setup_kernel(const float* __restrict__ W, int N) {
    int tid = blockIdx.x * blockDim.x + threadIdx.x;
    if (tid < N) g_cnt[tid] = 0;
    if (tid < F * F) g_wh[tid] = __float2half_rn(W[tid]);
}

// ---------------------------------------------------------------------------
// proj: h = x @ W via fp16 wmma (f32 accumulate). Block = 256 threads (8
// warps) computes a 16-row x 128-col tile; warp w owns cols [16w, 16w+16).
// A tile staged in smem (fp16), B read from g_wh (L1-hot 32KB), C staged in
// smem (f32) then rounded to fp16 g_h.
// ---------------------------------------------------------------------------
#define PROJ_ROWS 16
#define XSTRIDE 136
__global__ void proj_kernel(const float* __restrict__ x, int N) {
    __shared__ __align__(16) __half xs[PROJ_ROWS][XSTRIDE];
    __shared__ __align__(16) float  stage[PROJ_ROWS][XSTRIDE];

    int row0 = blockIdx.x * PROJ_ROWS;
    int t = threadIdx.x;
    int w = t >> 5;

    #pragma unroll
    for (int i = 0; i < 8; i++) {
        int idx = t + i * 256;
        int r = idx >> 7, c = idx & 127;
        int gr = row0 + r;
        xs[r][c] = __float2half_rn(gr < N ? x[(size_t)gr * F + c] : 0.0f);
    }
    __syncthreads();

    wmma::fragment<wmma::matrix_a, 16, 16, 16, __half, wmma::row_major> a;
    wmma::fragment<wmma::matrix_b, 16, 16, 16, __half, wmma::row_major> b;
    wmma::fragment<wmma::accumulator, 16, 16, 16, float> c;
    wmma::fill_fragment(c, 0.0f);

    #pragma unroll
    for (int kt = 0; kt < 8; kt++) {
        wmma::load_matrix_sync(a, &xs[0][kt * 16], XSTRIDE);
        wmma::load_matrix_sync(b, &g_wh[kt * 16 * F + w * 16], F);
        wmma::mma_sync(c, a, b, c);
    }

    wmma::store_matrix_sync(&stage[0][w * 16], c, XSTRIDE, wmma::mem_row_major);
    __syncthreads();

    #pragma unroll
    for (int i = 0; i < 8; i++) {
        int idx = t + i * 256;
        int r = idx >> 7, cc = idx & 127;
        int gr = row0 + r;
        if (gr < N) g_h[(size_t)gr * F + cc] = __float2half_rn(stage[r][cc]);
    }
}

// ---------------------------------------------------------------------------
// asrc: a_src/a_dst from fp16 h (unchanged).
// ---------------------------------------------------------------------------
#define AR 4
__global__ void asrc_kernel(const float* __restrict__ att_src,
                            const float* __restrict__ att_dst, int N) {
    int gw   = (blockIdx.x * blockDim.x + threadIdx.x) >> 5;
    int lane = threadIdx.x & 31;
    int row0 = gw * AR;
    if (row0 >= N) return;

    int head  = lane >> 3;
    int cbase = (lane & 7) * 4;
    float4 as = *reinterpret_cast<const float4*>(&att_src[head * 32 + cbase]);
    float4 ad = *reinterpret_cast<const float4*>(&att_dst[head * 32 + cbase]);

    u64 u[AR];
    #pragma unroll
    for (int i = 0; i < AR; i++) {
        int r = row0 + i;
        u[i] = (r < N) ? *reinterpret_cast<const u64*>(&g_h[(size_t)r * F + lane * 4]) : 0ULL;
    }

    #pragma unroll
    for (int i = 0; i < AR; i++) {
        int r = row0 + i;
        if (r >= N) break;
        float2 f01 = __half22float2(reinterpret_cast<__half2*>(&u[i])[0]);
        float2 f23 = __half22float2(reinterpret_cast<__half2*>(&u[i])[1]);
        float s = f01.x * as.x + f01.y * as.y + f23.x * as.z + f23.y * as.w;
        float d = f01.x * ad.x + f01.y * ad.y + f23.x * ad.z + f23.y * ad.w;
        #pragma unroll
        for (int o = 4; o > 0; o >>= 1) {
            s += __shfl_xor_sync(0xFFFFFFFFu, s, o);
            d += __shfl_xor_sync(0xFFFFFFFFu, d, o);
        }
        if ((lane & 7) == 0) {
            g_asrc[r * HEADS + head] = s;
            g_adst[r * HEADS + head] = d;
        }
    }
}

// ---------------------------------------------------------------------------
// CSR build (unchanged)
// ---------------------------------------------------------------------------
__global__ void hist_kernel(const int* __restrict__ ei, int E) {
    int e = blockIdx.x * blockDim.x + threadIdx.x;
    if (e < E) atomicAdd(&g_cnt[ei[E + e]], 1);
}

__global__ void scan1_kernel(int N) {
    __shared__ int sh[SCAN_BLK];
    int t = threadIdx.x;
    int g = blockIdx.x * SCAN_BLK + t;
    int v = (g < N) ? g_cnt[g] : 0;
    sh[t] = v;
    __syncthreads();
    #pragma unroll
    for (int o = 1; o < SCAN_BLK; o <<= 1) {
        int xv = (t >= o) ? sh[t - o] : 0;
        __syncthreads();
        if (t >= o) sh[t] += xv;
        __syncthreads();
    }
    if (g < N) g_off[g] = sh[t] - v;
    if (t == SCAN_BLK - 1) g_bsum[blockIdx.x] = sh[t];
}

__global__ void scan2_kernel(int NB) {
    if (threadIdx.x == 0 && blockIdx.x == 0) {
        int run = 0;
        for (int i = 0; i < NB; i++) { g_bsumex[i] = run; run += g_bsum[i]; }
    }
}

__global__ void scan3_kernel(int N, int E) {
    int g = blockIdx.x * blockDim.x + threadIdx.x;
    if (g < N) {
        int v = g_off[g] + g_bsumex[g / SCAN_BLK];
        g_off[g] = v;
        g_cur[g] = v;
    }
    if (g == 0) g_off[N] = E;
}

__global__ void fill_kernel(const int* __restrict__ ei, int E) {
    int e = blockIdx.x * blockDim.x + threadIdx.x;
    if (e < E) {
        int d = ei[E + e];
        int pos = atomicAdd(&g_cur[d], 1);
        g_csr[pos] = ei[e];
    }
}

// ---------------------------------------------------------------------------
// Gather (unchanged)
// ---------------------------------------------------------------------------
__device__ __forceinline__ float lrelu(float v) {
    return v > 0.0f ? v : NEG_SLOPE * v;
}
__device__ __forceinline__ void acc_h16(float4& acc, float p, const __half* hp) {
    u64 u = *reinterpret_cast<const u64*>(hp);
    __half2 h01 = reinterpret_cast<__half2*>(&u)[0];
    __half2 h23 = reinterpret_cast<__half2*>(&u)[1];
    float2 f01 = __half22float2(h01);
    float2 f23 = __half22float2(h23);
    acc.x = fmaf(p, f01.x, acc.x);
    acc.y = fmaf(p, f01.y, acc.y);
    acc.z = fmaf(p, f23.x, acc.z);
    acc.w = fmaf(p, f23.y, acc.w);
}

#define GW 8
__global__ void gather_kernel(float* __restrict__ out,
                              const float* __restrict__ bias, int N) {
    __shared__ int    ssrc[GW][32];
    __shared__ float4 sp[GW][32];
    int wip  = threadIdx.x >> 5;
    int i    = blockIdx.x * GW + wip;
    int lane = threadIdx.x & 31;
    if (i >= N) return;

    int head = lane >> 3;
    float4 adv = *reinterpret_cast<const float4*>(&g_adst[i * HEADS]);
    float ad_h = (head == 0) ? adv.x : (head == 1) ? adv.y : (head == 2) ? adv.z : adv.w;

    float p0 = __expf(lrelu(g_asrc[i * HEADS + head] + ad_h));
    float4 acc = make_float4(0.f, 0.f, 0.f, 0.f);
    acc_h16(acc, p0, &g_h[(size_t)i * F + lane * 4]);
    float den = p0;

    int beg = g_off[i];
    int end = g_off[i + 1];

    for (int base = beg; base < end; base += 32) {
        int k = base + lane;
        int sj = (k < end) ? g_csr[k] : 0;
        ssrc[wip][lane] = sj;
        float4 a = *reinterpret_cast<const float4*>(&g_asrc[sj * HEADS]);
        float4 p4;
        p4.x = __expf(lrelu(a.x + adv.x));
        p4.y = __expf(lrelu(a.y + adv.y));
        p4.z = __expf(lrelu(a.z + adv.z));
        p4.w = __expf(lrelu(a.w + adv.w));
        sp[wip][lane] = p4;
        __syncwarp();

        int cnt = end - base;
        if (cnt >= 32) {
            #pragma unroll 8
            for (int j = 0; j < 32; j++) {
                int s = ssrc[wip][j];
                float p = reinterpret_cast<const float*>(&sp[wip][j])[head];
                acc_h16(acc, p, &g_h[(size_t)s * F + lane * 4]);
                den += p;
            }
        } else {
            for (int j = 0; j < cnt; j++) {
                int s = ssrc[wip][j];
                float p = reinterpret_cast<const float*>(&sp[wip][j])[head];
                acc_h16(acc, p, &g_h[(size_t)s * F + lane * 4]);
                den += p;
            }
        }
        __syncwarp();
    }

    float inv = 1.0f / (den + 1e-16f);
    float4 b = *reinterpret_cast<const float4*>(&bias[lane * 4]);
    float4 r;
    r.x = fmaf(acc.x, inv, b.x);
    r.y = fmaf(acc.y, inv, b.y);
    r.z = fmaf(acc.z, inv, b.z);
    r.w = fmaf(acc.w, inv, b.w);
    *reinterpret_cast<float4*>(&out[i * F + lane * 4]) = r;
}

// ---------------------------------------------------------------------------
// Launch (proj kept at index 3 = ncu's profiled slot)
// ---------------------------------------------------------------------------
extern "C" void kernel_launch(void* const* d_in, const int* in_sizes, int n_in,
                              void* d_out, int out_size) {
    const float* x       = (const float*)d_in[0];
    const int*   ei      = (const int*)d_in[1];
    const float* W       = (const float*)d_in[2];
    const float* att_src = (const float*)d_in[3];
    const float* att_dst = (const float*)d_in[4];
    const float* bias    = (const float*)d_in[5];
    float*       out     = (float*)d_out;

    int N = in_sizes[0] / F;
    int E = in_sizes[1] / 2;
    int NB = (N + SCAN_BLK - 1) / SCAN_BLK;

    setup_kernel<<<(N + 255) / 256, 256>>>(W, N);                 // 0
    hist_kernel<<<(E + 255) / 256, 256>>>(ei, E);                 // 1
    scan1_kernel<<<NB, SCAN_BLK>>>(N);                            // 2
    proj_kernel<<<(N + PROJ_ROWS - 1) / PROJ_ROWS, 256>>>(x, N);  // 3 (profiled)
    scan2_kernel<<<1, 32>>>(NB);                                  // 4
    scan3_kernel<<<(N + 255) / 256, 256>>>(N, E);                 // 5
    fill_kernel<<<(E + 255) / 256, 256>>>(ei, E);                 // 6
    int awarps = (N + AR - 1) / AR;
    asrc_kernel<<<(awarps * 32 + 255) / 256, 256>>>(att_src, att_dst, N); // 7
    gather_kernel<<<(N + GW - 1) / GW, GW * 32>>>(out, bias, N);  // 8
}

// round 9
// speedup vs baseline: 3.4510x; 1.3134x over previous
#include <cuda_runtime.h>
#include <cuda_fp16.h>
#include <mma.h>
#include <math.h>

using namespace nvcuda;

// Fixed problem shape: N=100000, E=1600000, IN_F=128, H=4, C=32.
#define MAXN 100000
#define MAXE 1600000
#define F 128
#define HEADS 4
#define NEG_SLOPE 0.2f
#define SCAN_BLK 1024
#define MAX_NB ((MAXN + SCAN_BLK - 1) / SCAN_BLK)

typedef unsigned long long u64;

__device__ __align__(16) __half g_h[MAXN * F];         // projected features (fp16)
__device__ __align__(16) __half g_wh[F * F];           // W in fp16, natural [k][n]
__device__ __align__(16) float g_asrc[MAXN * HEADS];
__device__ __align__(16) float g_adst[MAXN * HEADS];
__device__ int g_cnt[MAXN];
__device__ int g_off[MAXN + 1];
__device__ int g_cur[MAXN];
__device__ int g_bsum[MAX_NB];
__device__ int g_bsumex[MAX_NB];
__device__ int g_csr[MAXE];

// ---------------------------------------------------------------------------
// setup: zero histogram + convert W to fp16
// ---------------------------------------------------------------------------
__global__ void setup_kernel(const float* __restrict__ W, int N) {
    int tid = blockIdx.x * blockDim.x + threadIdx.x;
    if (tid < N) g_cnt[tid] = 0;
    if (tid < F * F) g_wh[tid] = __float2half_rn(W[tid]);
}

// ---------------------------------------------------------------------------
// proj: h = x @ W via fp16 wmma, 64 rows x 128 cols per 256-thread block.
// B (full 128x128 W) staged in smem ONCE, hoisted into register fragments
// per warp; A row-tiles streamed through smem (LDSM path); C staged f32.
// ---------------------------------------------------------------------------
#define BST 136            // half-element stride for fp16 tiles (272B rows)
#define STF 136            // float stride for stage
#define PROJ_ROWS_BLK 64

__global__ __launch_bounds__(256, 1) void proj_kernel(const float* __restrict__ x, int N) {
    __shared__ __align__(16) __half bs[F * BST];          // 34816 B
    __shared__ __align__(16) __half as_[16 * BST];        // 4352 B
    __shared__ __align__(16) float  st[16 * STF];         // 8704 B

    int t = threadIdx.x;
    int w = t >> 5;

    // stage B (g_wh is 32KB): 2048 int4 loads
    const int4* wsrc = reinterpret_cast<const int4*>(g_wh);
    #pragma unroll
    for (int i = 0; i < 8; i++) {
        int idx = t + i * 256;          // 0..2047
        int k   = idx >> 4;             // 16 int4 per 128-half row
        int c8  = (idx & 15) * 8;
        *reinterpret_cast<int4*>(&bs[k * BST + c8]) = wsrc[idx];
    }
    __syncthreads();

    // hoist B fragments (8 k-tiles for this warp's 16 columns)
    wmma::fragment<wmma::matrix_b, 16, 16, 16, __half, wmma::row_major> bfrag[8];
    #pragma unroll
    for (int kt = 0; kt < 8; kt++)
        wmma::load_matrix_sync(bfrag[kt], &bs[kt * 16 * BST + w * 16], BST);

    int row0 = blockIdx.x * PROJ_ROWS_BLK;

    for (int rt = 0; rt < 4; rt++) {
        int rbase = row0 + rt * 16;

        // stage A row-tile: 16 rows x 128 f32 -> fp16 smem
        #pragma unroll
        for (int i = 0; i < 2; i++) {
            int idx = t + i * 256;      // 0..511 float4 slots
            int r = idx >> 5;           // 32 float4 per row
            int c = (idx & 31) * 4;
            int gr = rbase + r;
            float4 v = (gr < N) ? *reinterpret_cast<const float4*>(&x[(size_t)gr * F + c])
                                : make_float4(0.f, 0.f, 0.f, 0.f);
            __half2 h0 = __floats2half2_rn(v.x, v.y);
            __half2 h1 = __floats2half2_rn(v.z, v.w);
            *reinterpret_cast<__half2*>(&as_[r * BST + c])     = h0;
            *reinterpret_cast<__half2*>(&as_[r * BST + c + 2]) = h1;
        }
        __syncthreads();

        wmma::fragment<wmma::matrix_a, 16, 16, 16, __half, wmma::row_major> afrag;
        wmma::fragment<wmma::accumulator, 16, 16, 16, float> cfrag;
        wmma::fill_fragment(cfrag, 0.0f);
        #pragma unroll
        for (int kt = 0; kt < 8; kt++) {
            wmma::load_matrix_sync(afrag, &as_[kt * 16], BST);
            wmma::mma_sync(cfrag, afrag, bfrag[kt], cfrag);
        }
        wmma::store_matrix_sync(&st[w * 16], cfrag, STF, wmma::mem_row_major);
        __syncthreads();

        // write out 16x128 fp16
        #pragma unroll
        for (int i = 0; i < 2; i++) {
            int idx = t + i * 256;
            int r = idx >> 5;
            int c = (idx & 31) * 4;
            int gr = rbase + r;
            if (gr < N) {
                const float* sp = &st[r * STF + c];
                __half2 h0 = __floats2half2_rn(sp[0], sp[1]);
                __half2 h1 = __floats2half2_rn(sp[2], sp[3]);
                __half2 pair[2] = {h0, h1};
                *reinterpret_cast<u64*>(&g_h[(size_t)gr * F + c]) =
                    *reinterpret_cast<u64*>(pair);
            }
        }
        __syncthreads();
    }
}

// ---------------------------------------------------------------------------
// asrc: a_src/a_dst from fp16 h (unchanged).
// ---------------------------------------------------------------------------
#define AR 4
__global__ void asrc_kernel(const float* __restrict__ att_src,
                            const float* __restrict__ att_dst, int N) {
    int gw   = (blockIdx.x * blockDim.x + threadIdx.x) >> 5;
    int lane = threadIdx.x & 31;
    int row0 = gw * AR;
    if (row0 >= N) return;

    int head  = lane >> 3;
    int cbase = (lane & 7) * 4;
    float4 as = *reinterpret_cast<const float4*>(&att_src[head * 32 + cbase]);
    float4 ad = *reinterpret_cast<const float4*>(&att_dst[head * 32 + cbase]);

    u64 u[AR];
    #pragma unroll
    for (int i = 0; i < AR; i++) {
        int r = row0 + i;
        u[i] = (r < N) ? *reinterpret_cast<const u64*>(&g_h[(size_t)r * F + lane * 4]) : 0ULL;
    }

    #pragma unroll
    for (int i = 0; i < AR; i++) {
        int r = row0 + i;
        if (r >= N) break;
        float2 f01 = __half22float2(reinterpret_cast<__half2*>(&u[i])[0]);
        float2 f23 = __half22float2(reinterpret_cast<__half2*>(&u[i])[1]);
        float s = f01.x * as.x + f01.y * as.y + f23.x * as.z + f23.y * as.w;
        float d = f01.x * ad.x + f01.y * ad.y + f23.x * ad.z + f23.y * ad.w;
        #pragma unroll
        for (int o = 4; o > 0; o >>= 1) {
            s += __shfl_xor_sync(0xFFFFFFFFu, s, o);
            d += __shfl_xor_sync(0xFFFFFFFFu, d, o);
        }
        if ((lane & 7) == 0) {
            g_asrc[r * HEADS + head] = s;
            g_adst[r * HEADS + head] = d;
        }
    }
}

// ---------------------------------------------------------------------------
// CSR build (unchanged)
// ---------------------------------------------------------------------------
__global__ void hist_kernel(const int* __restrict__ ei, int E) {
    int e = blockIdx.x * blockDim.x + threadIdx.x;
    if (e < E) atomicAdd(&g_cnt[ei[E + e]], 1);
}

__global__ void scan1_kernel(int N) {
    __shared__ int sh[SCAN_BLK];
    int t = threadIdx.x;
    int g = blockIdx.x * SCAN_BLK + t;
    int v = (g < N) ? g_cnt[g] : 0;
    sh[t] = v;
    __syncthreads();
    #pragma unroll
    for (int o = 1; o < SCAN_BLK; o <<= 1) {
        int xv = (t >= o) ? sh[t - o] : 0;
        __syncthreads();
        if (t >= o) sh[t] += xv;
        __syncthreads();
    }
    if (g < N) g_off[g] = sh[t] - v;
    if (t == SCAN_BLK - 1) g_bsum[blockIdx.x] = sh[t];
}

__global__ void scan2_kernel(int NB) {
    if (threadIdx.x == 0 && blockIdx.x == 0) {
        int run = 0;
        for (int i = 0; i < NB; i++) { g_bsumex[i] = run; run += g_bsum[i]; }
    }
}

__global__ void scan3_kernel(int N, int E) {
    int g = blockIdx.x * blockDim.x + threadIdx.x;
    if (g < N) {
        int v = g_off[g] + g_bsumex[g / SCAN_BLK];
        g_off[g] = v;
        g_cur[g] = v;
    }
    if (g == 0) g_off[N] = E;
}

__global__ void fill_kernel(const int* __restrict__ ei, int E) {
    int e = blockIdx.x * blockDim.x + threadIdx.x;
    if (e < E) {
        int d = ei[E + e];
        int pos = atomicAdd(&g_cur[d], 1);
        g_csr[pos] = ei[e];
    }
}

// ---------------------------------------------------------------------------
// Gather (unchanged)
// ---------------------------------------------------------------------------
__device__ __forceinline__ float lrelu(float v) {
    return v > 0.0f ? v : NEG_SLOPE * v;
}
__device__ __forceinline__ void acc_h16(float4& acc, float p, const __half* hp) {
    u64 u = *reinterpret_cast<const u64*>(hp);
    __half2 h01 = reinterpret_cast<__half2*>(&u)[0];
    __half2 h23 = reinterpret_cast<__half2*>(&u)[1];
    float2 f01 = __half22float2(h01);
    float2 f23 = __half22float2(h23);
    acc.x = fmaf(p, f01.x, acc.x);
    acc.y = fmaf(p, f01.y, acc.y);
    acc.z = fmaf(p, f23.x, acc.z);
    acc.w = fmaf(p, f23.y, acc.w);
}

#define GW 8
__global__ void gather_kernel(float* __restrict__ out,
                              const float* __restrict__ bias, int N) {
    __shared__ int    ssrc[GW][32];
    __shared__ float4 sp[GW][32];
    int wip  = threadIdx.x >> 5;
    int i    = blockIdx.x * GW + wip;
    int lane = threadIdx.x & 31;
    if (i >= N) return;

    int head = lane >> 3;
    float4 adv = *reinterpret_cast<const float4*>(&g_adst[i * HEADS]);
    float ad_h = (head == 0) ? adv.x : (head == 1) ? adv.y : (head == 2) ? adv.z : adv.w;

    float p0 = __expf(lrelu(g_asrc[i * HEADS + head] + ad_h));
    float4 acc = make_float4(0.f, 0.f, 0.f, 0.f);
    acc_h16(acc, p0, &g_h[(size_t)i * F + lane * 4]);
    float den = p0;

    int beg = g_off[i];
    int end = g_off[i + 1];

    for (int base = beg; base < end; base += 32) {
        int k = base + lane;
        int sj = (k < end) ? g_csr[k] : 0;
        ssrc[wip][lane] = sj;
        float4 a = *reinterpret_cast<const float4*>(&g_asrc[sj * HEADS]);
        float4 p4;
        p4.x = __expf(lrelu(a.x + adv.x));
        p4.y = __expf(lrelu(a.y + adv.y));
        p4.z = __expf(lrelu(a.z + adv.z));
        p4.w = __expf(lrelu(a.w + adv.w));
        sp[wip][lane] = p4;
        __syncwarp();

        int cnt = end - base;
        if (cnt >= 32) {
            #pragma unroll 8
            for (int j = 0; j < 32; j++) {
                int s = ssrc[wip][j];
                float p = reinterpret_cast<const float*>(&sp[wip][j])[head];
                acc_h16(acc, p, &g_h[(size_t)s * F + lane * 4]);
                den += p;
            }
        } else {
            for (int j = 0; j < cnt; j++) {
                int s = ssrc[wip][j];
                float p = reinterpret_cast<const float*>(&sp[wip][j])[head];
                acc_h16(acc, p, &g_h[(size_t)s * F + lane * 4]);
                den += p;
            }
        }
        __syncwarp();
    }

    float inv = 1.0f / (den + 1e-16f);
    float4 b = *reinterpret_cast<const float4*>(&bias[lane * 4]);
    float4 r;
    r.x = fmaf(acc.x, inv, b.x);
    r.y = fmaf(acc.y, inv, b.y);
    r.z = fmaf(acc.z, inv, b.z);
    r.w = fmaf(acc.w, inv, b.w);
    *reinterpret_cast<float4*>(&out[i * F + lane * 4]) = r;
}

// ---------------------------------------------------------------------------
// Launch (proj kept at index 3 = ncu's profiled slot)
// ---------------------------------------------------------------------------
extern "C" void kernel_launch(void* const* d_in, const int* in_sizes, int n_in,
                              void* d_out, int out_size) {
    const float* x       = (const float*)d_in[0];
    const int*   ei      = (const int*)d_in[1];
    const float* W       = (const float*)d_in[2];
    const float* att_src = (const float*)d_in[3];
    const float* att_dst = (const float*)d_in[4];
    const float* bias    = (const float*)d_in[5];
    float*       out     = (float*)d_out;

    int N = in_sizes[0] / F;
    int E = in_sizes[1] / 2;
    int NB = (N + SCAN_BLK - 1) / SCAN_BLK;

    setup_kernel<<<(N + 255) / 256, 256>>>(W, N);                 // 0
    hist_kernel<<<(E + 255) / 256, 256>>>(ei, E);                 // 1
    scan1_kernel<<<NB, SCAN_BLK>>>(N);                            // 2
    proj_kernel<<<(N + PROJ_ROWS_BLK - 1) / PROJ_ROWS_BLK, 256>>>(x, N); // 3 (profiled)
    scan2_kernel<<<1, 32>>>(NB);                                  // 4
    scan3_kernel<<<(N + 255) / 256, 256>>>(N, E);                 // 5
    fill_kernel<<<(E + 255) / 256, 256>>>(ei, E);                 // 6
    int awarps = (N + AR - 1) / AR;
    asrc_kernel<<<(awarps * 32 + 255) / 256, 256>>>(att_src, att_dst, N); // 7
    gather_kernel<<<(N + GW - 1) / GW, GW * 32>>>(out, bias, N);  // 8
}